// round 2
// baseline (speedup 1.0000x reference)
#include <cuda_runtime.h>
#include <math.h>

// Problem constants
#define B_   32
#define T_   128
#define H_   768
#define IN_  256
#define H2_  1536

// exp(-1/20)
#define ALPHA_   0.951229424500714f
#define OMA_     0.048770575499286f   // 1 - alpha
#define DTR_     0.951229424500714f   // decay_trace
#define OMD_     0.048770575499286f
#define ETA_     0.1f
#define CIKV_    0.02f                // 0.2 * eta

// Output offsets (floats): mem | keys | vals
#define OUT_MEM_   0
#define OUT_KEYS_  18874368           // 32*768*768
#define OUT_VALS_  22020096           // + 32*128*768

// Scratch (static device arrays; no runtime allocation)
__device__ float g_i[B_ * T_ * H2_];        // input projection (b,t,2H)
__device__ float g_key[B_ * T_ * H_];       // key outputs
__device__ float g_ktr[B_ * T_ * H_];       // key traces
__device__ float g_vtr[B_ * T_ * H_];       // value traces
__device__ float g_Apart[6 * B_ * T_ * T_]; // K-split partials of A

// ---------------------------------------------------------------------------
// K1: input GEMM  g_i[m][n] = sum_k x[m][k] * W[n][k]
//     M = B*T = 4096, N = 2H = 1536, K = 256
//     128x128 tile, 256 threads, 8x8 microtile, BK = 32
// ---------------------------------------------------------------------------
__global__ __launch_bounds__(256) void k1_gemm_in(
    const float* __restrict__ x, const float* __restrict__ W)
{
    __shared__ float As[32][128];  // [k][m]
    __shared__ float Bs[32][128];  // [k][n]

    const int m0 = blockIdx.y * 128;
    const int n0 = blockIdx.x * 128;
    const int tid = threadIdx.x;
    const int tr = tid >> 4;   // 0..15  (m sub-block)
    const int tc = tid & 15;   // 0..15  (n sub-block)

    float acc[8][8];
#pragma unroll
    for (int i = 0; i < 8; i++)
#pragma unroll
        for (int j = 0; j < 8; j++) acc[i][j] = 0.f;

    for (int k0 = 0; k0 < IN_; k0 += 32) {
        // load A tile (x): 128 rows x 32 k, transposed into As[k][m]
#pragma unroll
        for (int l = 0; l < 4; l++) {
            int idx = tid + l * 256;       // 0..1023 float4 slots
            int row = idx >> 3;            // m within tile
            int c4  = idx & 7;             // which float4 along k
            float4 v = *(const float4*)&x[(m0 + row) * IN_ + k0 + c4 * 4];
            As[c4 * 4 + 0][row] = v.x;
            As[c4 * 4 + 1][row] = v.y;
            As[c4 * 4 + 2][row] = v.z;
            As[c4 * 4 + 3][row] = v.w;
        }
        // load B tile (W): 128 rows x 32 k, transposed into Bs[k][n]
#pragma unroll
        for (int l = 0; l < 4; l++) {
            int idx = tid + l * 256;
            int row = idx >> 3;
            int c4  = idx & 7;
            float4 v = *(const float4*)&W[(n0 + row) * IN_ + k0 + c4 * 4];
            Bs[c4 * 4 + 0][row] = v.x;
            Bs[c4 * 4 + 1][row] = v.y;
            Bs[c4 * 4 + 2][row] = v.z;
            Bs[c4 * 4 + 3][row] = v.w;
        }
        __syncthreads();
#pragma unroll
        for (int k = 0; k < 32; k++) {
            float4 a0 = *(const float4*)&As[k][tr * 8];
            float4 a1 = *(const float4*)&As[k][tr * 8 + 4];
            float4 b0 = *(const float4*)&Bs[k][tc * 8];
            float4 b1 = *(const float4*)&Bs[k][tc * 8 + 4];
            float a[8] = {a0.x, a0.y, a0.z, a0.w, a1.x, a1.y, a1.z, a1.w};
            float b[8] = {b0.x, b0.y, b0.z, b0.w, b1.x, b1.y, b1.z, b1.w};
#pragma unroll
            for (int i = 0; i < 8; i++)
#pragma unroll
                for (int j = 0; j < 8; j++) acc[i][j] = fmaf(a[i], b[j], acc[i][j]);
        }
        __syncthreads();
    }

#pragma unroll
    for (int i = 0; i < 8; i++) {
        float* dst = &g_i[(m0 + tr * 8 + i) * H2_ + n0 + tc * 8];
        *(float4*)&dst[0] = make_float4(acc[i][0], acc[i][1], acc[i][2], acc[i][3]);
        *(float4*)&dst[4] = make_float4(acc[i][4], acc[i][5], acc[i][6], acc[i][7]);
    }
}

// ---------------------------------------------------------------------------
// K2: key-side elementwise scan. One thread per (b,h).
//     kv = a*kv + (1-a)*ik;  key = tanh(kv);  ktr = d*ktr + (1-d)*key
//     Writes g_key, g_ktr, and keys output.
// ---------------------------------------------------------------------------
__global__ __launch_bounds__(256) void k2_scan_key(float* __restrict__ out)
{
    const int b  = blockIdx.x / 3;
    const int h  = (blockIdx.x % 3) * 256 + threadIdx.x;

    const float* ik = &g_i[(b * T_) * H2_ + h];
    float* keyp  = &g_key[(b * T_) * H_ + h];
    float* ktrp  = &g_ktr[(b * T_) * H_ + h];
    float* keyso = &out[OUT_KEYS_ + (b * T_) * H_ + h];

    float kv = 0.f, ktr = 0.f;
#pragma unroll 4
    for (int t = 0; t < T_; t++) {
        kv = ALPHA_ * kv + OMA_ * ik[t * H2_];
        float key = tanhf(kv);
        ktr = DTR_ * ktr + OMD_ * key;
        keyp[t * H_]  = key;
        ktrp[t * H_]  = ktr;
        keyso[t * H_] = key;
    }
}

// ---------------------------------------------------------------------------
// K3: A partials.  Apart[p][b][t][s] = sum_{k in p-th 128-chunk} key[b,t,k]*ktr[b,s,k]
//     grid (6, 32); 128x128 tile; 256 threads; 8x8 micro; BK = 32
// ---------------------------------------------------------------------------
__global__ __launch_bounds__(256) void k3_gemm_A()
{
    __shared__ float As[32][128];  // [k][t]
    __shared__ float Bs[32][128];  // [k][s]

    const int p = blockIdx.x;
    const int b = blockIdx.y;
    const int tid = threadIdx.x;
    const int tr = tid >> 4;
    const int tc = tid & 15;

    const float* keyb = &g_key[b * T_ * H_ + p * 128];
    const float* ktrb = &g_ktr[b * T_ * H_ + p * 128];

    float acc[8][8];
#pragma unroll
    for (int i = 0; i < 8; i++)
#pragma unroll
        for (int j = 0; j < 8; j++) acc[i][j] = 0.f;

    for (int k0 = 0; k0 < 128; k0 += 32) {
#pragma unroll
        for (int l = 0; l < 4; l++) {
            int idx = tid + l * 256;
            int row = idx >> 3;
            int c4  = idx & 7;
            float4 v = *(const float4*)&keyb[row * H_ + k0 + c4 * 4];
            As[c4 * 4 + 0][row] = v.x;
            As[c4 * 4 + 1][row] = v.y;
            As[c4 * 4 + 2][row] = v.z;
            As[c4 * 4 + 3][row] = v.w;
        }
#pragma unroll
        for (int l = 0; l < 4; l++) {
            int idx = tid + l * 256;
            int row = idx >> 3;
            int c4  = idx & 7;
            float4 v = *(const float4*)&ktrb[row * H_ + k0 + c4 * 4];
            Bs[c4 * 4 + 0][row] = v.x;
            Bs[c4 * 4 + 1][row] = v.y;
            Bs[c4 * 4 + 2][row] = v.z;
            Bs[c4 * 4 + 3][row] = v.w;
        }
        __syncthreads();
#pragma unroll
        for (int k = 0; k < 32; k++) {
            float4 a0 = *(const float4*)&As[k][tr * 8];
            float4 a1 = *(const float4*)&As[k][tr * 8 + 4];
            float4 b0 = *(const float4*)&Bs[k][tc * 8];
            float4 b1 = *(const float4*)&Bs[k][tc * 8 + 4];
            float a[8] = {a0.x, a0.y, a0.z, a0.w, a1.x, a1.y, a1.z, a1.w};
            float bb[8] = {b0.x, b0.y, b0.z, b0.w, b1.x, b1.y, b1.z, b1.w};
#pragma unroll
            for (int i = 0; i < 8; i++)
#pragma unroll
                for (int j = 0; j < 8; j++) acc[i][j] = fmaf(a[i], bb[j], acc[i][j]);
        }
        __syncthreads();
    }

    float* dst0 = &g_Apart[(size_t)(p * B_ + b) * (T_ * T_)];
#pragma unroll
    for (int i = 0; i < 8; i++) {
        float* dst = &dst0[(tr * 8 + i) * 128 + tc * 8];
        *(float4*)&dst[0] = make_float4(acc[i][0], acc[i][1], acc[i][2], acc[i][3]);
        *(float4*)&dst[4] = make_float4(acc[i][4], acc[i][5], acc[i][6], acc[i][7]);
    }
}

// ---------------------------------------------------------------------------
// K4: value-side sequential scan. grid = 32 batches x 6 h-blocks, 128 threads.
//     Each thread owns one h. vtr history private per thread -> no per-step sync.
//     SMEM: A[128][128] (64KB) + vtr history [128][128] (64KB) = 128KB dynamic.
// ---------------------------------------------------------------------------
__global__ __launch_bounds__(128) void k4_scan_val(float* __restrict__ out)
{
    extern __shared__ float sm[];
    float* A_s   = sm;          // 16384 floats
    float* vtr_s = sm + 16384;  // [t][tid]

    const int b  = blockIdx.x / 6;
    const int hb = blockIdx.x % 6;
    const int tid = threadIdx.x;
    const int h = hb * 128 + tid;

    // sum the 6 K-split partials of A into smem
    const float* ap = &g_Apart[(size_t)b * (T_ * T_)];
    for (int e = tid; e < T_ * T_; e += 128) {
        float s = 0.f;
#pragma unroll
        for (int p = 0; p < 6; p++) s += ap[(size_t)p * B_ * T_ * T_ + e];
        A_s[e] = s;
    }
    __syncthreads();

    const float* ivp = &g_i[b * T_ * H2_ + H_ + h];
    float* valso = &out[OUT_VALS_ + (b * T_) * H_ + h];
    float* vtrg  = &g_vtr[(b * T_) * H_ + h];

    float vv = 0.f, vtr = 0.f;
    for (int t = 0; t < T_; t++) {
        const float* Arow = &A_s[t * 128];
        float s0 = 0.f, s1 = 0.f, s2 = 0.f, s3 = 0.f;
        int s = 0;
        for (; s + 4 <= t; s += 4) {
            s0 = fmaf(Arow[s + 0], vtr_s[(s + 0) * 128 + tid], s0);
            s1 = fmaf(Arow[s + 1], vtr_s[(s + 1) * 128 + tid], s1);
            s2 = fmaf(Arow[s + 2], vtr_s[(s + 2) * 128 + tid], s2);
            s3 = fmaf(Arow[s + 3], vtr_s[(s + 3) * 128 + tid], s3);
        }
        for (; s < t; s++) s0 = fmaf(Arow[s], vtr_s[s * 128 + tid], s0);
        float ikv = CIKV_ * ((s0 + s1) + (s2 + s3));

        vv = ALPHA_ * vv + OMA_ * (ivp[t * H2_] + ikv);
        float val = tanhf(vv);
        valso[t * H_] = val;
        vtr = DTR_ * vtr + OMD_ * val;
        vtr_s[t * 128 + tid] = vtr;  // read only by this same thread later
        vtrg[t * H_] = vtr;
    }
}

// ---------------------------------------------------------------------------
// K5: final memory GEMM.  mem[b][i][j] = eta * sum_s vtr[b,s,i]*ktr[b,s,j]
//     grid (6,6,32); 128x128 tile; K = 128 (s); BK = 32; conflict-free loads.
// ---------------------------------------------------------------------------
__global__ __launch_bounds__(256) void k5_gemm_mem(float* __restrict__ out)
{
    __shared__ float As[32][128];  // [s][i]
    __shared__ float Bs[32][128];  // [s][j]

    const int b  = blockIdx.z;
    const int i0 = blockIdx.y * 128;
    const int j0 = blockIdx.x * 128;
    const int tid = threadIdx.x;
    const int tr = tid >> 4;
    const int tc = tid & 15;

    const float* vtrb = &g_vtr[b * T_ * H_];
    const float* ktrb = &g_ktr[b * T_ * H_];

    float acc[8][8];
#pragma unroll
    for (int i = 0; i < 8; i++)
#pragma unroll
        for (int j = 0; j < 8; j++) acc[i][j] = 0.f;

    for (int s0 = 0; s0 < T_; s0 += 32) {
#pragma unroll
        for (int l = 0; l < 4; l++) {
            int idx = tid + l * 256;   // 1024 float4 slots
            int s  = idx >> 5;         // 32 float4 per row
            int c4 = idx & 31;
            *(float4*)&As[s][c4 * 4] =
                *(const float4*)&vtrb[(s0 + s) * H_ + i0 + c4 * 4];
        }
#pragma unroll
        for (int l = 0; l < 4; l++) {
            int idx = tid + l * 256;
            int s  = idx >> 5;
            int c4 = idx & 31;
            *(float4*)&Bs[s][c4 * 4] =
                *(const float4*)&ktrb[(s0 + s) * H_ + j0 + c4 * 4];
        }
        __syncthreads();
#pragma unroll
        for (int k = 0; k < 32; k++) {
            float4 a0 = *(const float4*)&As[k][tr * 8];
            float4 a1 = *(const float4*)&As[k][tr * 8 + 4];
            float4 b0 = *(const float4*)&Bs[k][tc * 8];
            float4 b1 = *(const float4*)&Bs[k][tc * 8 + 4];
            float a[8] = {a0.x, a0.y, a0.z, a0.w, a1.x, a1.y, a1.z, a1.w};
            float bb[8] = {b0.x, b0.y, b0.z, b0.w, b1.x, b1.y, b1.z, b1.w};
#pragma unroll
            for (int i = 0; i < 8; i++)
#pragma unroll
                for (int j = 0; j < 8; j++) acc[i][j] = fmaf(a[i], bb[j], acc[i][j]);
        }
        __syncthreads();
    }

#pragma unroll
    for (int i = 0; i < 8; i++) {
        float* dst = &out[(size_t)b * (H_ * H_) + (i0 + tr * 8 + i) * H_ + j0 + tc * 8];
        *(float4*)&dst[0] = make_float4(ETA_ * acc[i][0], ETA_ * acc[i][1],
                                        ETA_ * acc[i][2], ETA_ * acc[i][3]);
        *(float4*)&dst[4] = make_float4(ETA_ * acc[i][4], ETA_ * acc[i][5],
                                        ETA_ * acc[i][6], ETA_ * acc[i][7]);
    }
}

// ---------------------------------------------------------------------------
extern "C" void kernel_launch(void* const* d_in, const int* in_sizes, int n_in,
                              void* d_out, int out_size)
{
    const float* x = (const float*)d_in[0];   // (32,128,256)
    const float* W = (const float*)d_in[1];   // (1536,256)
    float* out = (float*)d_out;               // mem | keys | vals

    // K4 needs 128KB dynamic smem. Idempotent; persists from the correctness
    // call even if a later call's attempt is a no-op. Error intentionally ignored.
    (void)cudaFuncSetAttribute(k4_scan_val,
                               cudaFuncAttributeMaxDynamicSharedMemorySize,
                               131072);

    k1_gemm_in<<<dim3(12, 32), 256>>>(x, W);
    k2_scan_key<<<96, 256>>>(out);
    k3_gemm_A<<<dim3(6, 32), 256>>>();
    k4_scan_val<<<192, 128, 131072>>>(out);
    k5_gemm_mem<<<dim3(6, 6, 32), 256>>>(out);
}

// round 3
// speedup vs baseline: 1.5345x; 1.5345x over previous
#include <cuda_runtime.h>
#include <math.h>

// Problem constants
#define B_   32
#define T_   128
#define H_   768
#define IN_  256
#define H2_  1536

// exp(-1/20)
#define ALPHA_   0.951229424500714f
#define OMA_     0.048770575499286f   // 1 - alpha
#define DTR_     0.951229424500714f   // decay_trace
#define OMD_     0.048770575499286f
#define ETA_     0.1f
#define CIKV_    0.02f                // 0.2 * eta

// Output offsets (floats): mem | keys | vals
#define OUT_MEM_   0
#define OUT_KEYS_  18874368           // 32*768*768
#define OUT_VALS_  22020096           // + 32*128*768

// Scratch (static device arrays; no runtime allocation)
__device__ float g_i[B_ * T_ * H2_];        // input projection (b,t,2H)
__device__ float g_key[B_ * T_ * H_];       // key outputs
__device__ float g_ktr[B_ * T_ * H_];       // key traces
__device__ float g_vtr[B_ * T_ * H_];       // value traces
__device__ float g_Apart[6 * B_ * T_ * T_]; // K-split partials of A

__device__ __forceinline__ float tanh_fast(float x) {
    float y;
    asm("tanh.approx.f32 %0, %1;" : "=f"(y) : "f"(x));
    return y;
}

// ---------------------------------------------------------------------------
// K1: input GEMM  g_i[m][n] = sum_k x[m][k] * W[n][k]
//     M = B*T = 4096, N = 2H = 1536, K = 256
// ---------------------------------------------------------------------------
__global__ __launch_bounds__(256) void k1_gemm_in(
    const float* __restrict__ x, const float* __restrict__ W)
{
    __shared__ float As[32][128];  // [k][m]
    __shared__ float Bs[32][128];  // [k][n]

    const int m0 = blockIdx.y * 128;
    const int n0 = blockIdx.x * 128;
    const int tid = threadIdx.x;
    const int tr = tid >> 4;
    const int tc = tid & 15;

    float acc[8][8];
#pragma unroll
    for (int i = 0; i < 8; i++)
#pragma unroll
        for (int j = 0; j < 8; j++) acc[i][j] = 0.f;

    for (int k0 = 0; k0 < IN_; k0 += 32) {
#pragma unroll
        for (int l = 0; l < 4; l++) {
            int idx = tid + l * 256;
            int row = idx >> 3;
            int c4  = idx & 7;
            float4 v = *(const float4*)&x[(m0 + row) * IN_ + k0 + c4 * 4];
            As[c4 * 4 + 0][row] = v.x;
            As[c4 * 4 + 1][row] = v.y;
            As[c4 * 4 + 2][row] = v.z;
            As[c4 * 4 + 3][row] = v.w;
        }
#pragma unroll
        for (int l = 0; l < 4; l++) {
            int idx = tid + l * 256;
            int row = idx >> 3;
            int c4  = idx & 7;
            float4 v = *(const float4*)&W[(n0 + row) * IN_ + k0 + c4 * 4];
            Bs[c4 * 4 + 0][row] = v.x;
            Bs[c4 * 4 + 1][row] = v.y;
            Bs[c4 * 4 + 2][row] = v.z;
            Bs[c4 * 4 + 3][row] = v.w;
        }
        __syncthreads();
#pragma unroll
        for (int k = 0; k < 32; k++) {
            float4 a0 = *(const float4*)&As[k][tr * 8];
            float4 a1 = *(const float4*)&As[k][tr * 8 + 4];
            float4 b0 = *(const float4*)&Bs[k][tc * 8];
            float4 b1 = *(const float4*)&Bs[k][tc * 8 + 4];
            float a[8] = {a0.x, a0.y, a0.z, a0.w, a1.x, a1.y, a1.z, a1.w};
            float b[8] = {b0.x, b0.y, b0.z, b0.w, b1.x, b1.y, b1.z, b1.w};
#pragma unroll
            for (int i = 0; i < 8; i++)
#pragma unroll
                for (int j = 0; j < 8; j++) acc[i][j] = fmaf(a[i], b[j], acc[i][j]);
        }
        __syncthreads();
    }

#pragma unroll
    for (int i = 0; i < 8; i++) {
        float* dst = &g_i[(m0 + tr * 8 + i) * H2_ + n0 + tc * 8];
        *(float4*)&dst[0] = make_float4(acc[i][0], acc[i][1], acc[i][2], acc[i][3]);
        *(float4*)&dst[4] = make_float4(acc[i][4], acc[i][5], acc[i][6], acc[i][7]);
    }
}

// ---------------------------------------------------------------------------
// K2: key-side elementwise scan. One thread per (b,h).
// ---------------------------------------------------------------------------
__global__ __launch_bounds__(256) void k2_scan_key(float* __restrict__ out)
{
    const int b  = blockIdx.x / 3;
    const int h  = (blockIdx.x % 3) * 256 + threadIdx.x;

    const float* ik = &g_i[(b * T_) * H2_ + h];
    float* keyp  = &g_key[(b * T_) * H_ + h];
    float* ktrp  = &g_ktr[(b * T_) * H_ + h];
    float* keyso = &out[OUT_KEYS_ + (b * T_) * H_ + h];

    float kv = 0.f, ktr = 0.f;
#pragma unroll 4
    for (int t = 0; t < T_; t++) {
        kv = ALPHA_ * kv + OMA_ * ik[t * H2_];
        float key = tanh_fast(kv);
        ktr = DTR_ * ktr + OMD_ * key;
        keyp[t * H_]  = key;
        ktrp[t * H_]  = ktr;
        keyso[t * H_] = key;
    }
}

// ---------------------------------------------------------------------------
// K3: A partials.  Apart[p][b][t][s] = sum_{k in p-th 128-chunk} key[b,t,k]*ktr[b,s,k]
// ---------------------------------------------------------------------------
__global__ __launch_bounds__(256) void k3_gemm_A()
{
    __shared__ float As[32][128];
    __shared__ float Bs[32][128];

    const int p = blockIdx.x;
    const int b = blockIdx.y;
    const int tid = threadIdx.x;
    const int tr = tid >> 4;
    const int tc = tid & 15;

    const float* keyb = &g_key[b * T_ * H_ + p * 128];
    const float* ktrb = &g_ktr[b * T_ * H_ + p * 128];

    float acc[8][8];
#pragma unroll
    for (int i = 0; i < 8; i++)
#pragma unroll
        for (int j = 0; j < 8; j++) acc[i][j] = 0.f;

    for (int k0 = 0; k0 < 128; k0 += 32) {
#pragma unroll
        for (int l = 0; l < 4; l++) {
            int idx = tid + l * 256;
            int row = idx >> 3;
            int c4  = idx & 7;
            float4 v = *(const float4*)&keyb[row * H_ + k0 + c4 * 4];
            As[c4 * 4 + 0][row] = v.x;
            As[c4 * 4 + 1][row] = v.y;
            As[c4 * 4 + 2][row] = v.z;
            As[c4 * 4 + 3][row] = v.w;
        }
#pragma unroll
        for (int l = 0; l < 4; l++) {
            int idx = tid + l * 256;
            int row = idx >> 3;
            int c4  = idx & 7;
            float4 v = *(const float4*)&ktrb[row * H_ + k0 + c4 * 4];
            Bs[c4 * 4 + 0][row] = v.x;
            Bs[c4 * 4 + 1][row] = v.y;
            Bs[c4 * 4 + 2][row] = v.z;
            Bs[c4 * 4 + 3][row] = v.w;
        }
        __syncthreads();
#pragma unroll
        for (int k = 0; k < 32; k++) {
            float4 a0 = *(const float4*)&As[k][tr * 8];
            float4 a1 = *(const float4*)&As[k][tr * 8 + 4];
            float4 b0 = *(const float4*)&Bs[k][tc * 8];
            float4 b1 = *(const float4*)&Bs[k][tc * 8 + 4];
            float a[8] = {a0.x, a0.y, a0.z, a0.w, a1.x, a1.y, a1.z, a1.w};
            float bb[8] = {b0.x, b0.y, b0.z, b0.w, b1.x, b1.y, b1.z, b1.w};
#pragma unroll
            for (int i = 0; i < 8; i++)
#pragma unroll
                for (int j = 0; j < 8; j++) acc[i][j] = fmaf(a[i], bb[j], acc[i][j]);
        }
        __syncthreads();
    }

    float* dst0 = &g_Apart[(size_t)(p * B_ + b) * (T_ * T_)];
#pragma unroll
    for (int i = 0; i < 8; i++) {
        float* dst = &dst0[(tr * 8 + i) * 128 + tc * 8];
        *(float4*)&dst[0] = make_float4(acc[i][0], acc[i][1], acc[i][2], acc[i][3]);
        *(float4*)&dst[4] = make_float4(acc[i][4], acc[i][5], acc[i][6], acc[i][7]);
    }
}

// ---------------------------------------------------------------------------
// K4: value-side sequential scan, BLOCKED.
//     grid = 32 batches x 3 h-blocks, 256 threads. One thread per h.
//     t split into blocks of 16. Cross-block contribution (s < t0) computed
//     densely with 16 register accumulators (16-way ILP, vtr loaded once per
//     s and reused across 16 t's, A rows via LDS.128 broadcast). Only the
//     intra-block triangle stays sequential.
//     Dyn SMEM: A[128][128] 64KB + vtr history [128][256] 128KB = 192KB.
// ---------------------------------------------------------------------------
#define K4_THREADS 256
#define K4_BLK 16

__global__ __launch_bounds__(K4_THREADS) void k4_scan_val(float* __restrict__ out)
{
    extern __shared__ float sm[];
    float* A_s   = sm;              // 16384 floats
    float* vtr_s = sm + T_ * T_;    // [s][K4_THREADS]

    const int b   = blockIdx.x / 3;
    const int hb  = blockIdx.x % 3;
    const int tid = threadIdx.x;
    const int h   = hb * K4_THREADS + tid;

    // sum the 6 K-split partials of A into smem (float4)
    {
        const float* ap = &g_Apart[(size_t)b * (T_ * T_)];
        for (int e = tid * 4; e < T_ * T_; e += K4_THREADS * 4) {
            float4 s = *(const float4*)&ap[e];
#pragma unroll
            for (int p = 1; p < 6; p++) {
                float4 v = *(const float4*)&ap[(size_t)p * B_ * T_ * T_ + e];
                s.x += v.x; s.y += v.y; s.z += v.z; s.w += v.w;
            }
            *(float4*)&A_s[e] = s;
        }
    }
    __syncthreads();

    const float* ivp = &g_i[b * T_ * H2_ + H_ + h];
    float* valso = &out[OUT_VALS_ + (b * T_) * H_ + h];
    float* vtrg  = &g_vtr[(b * T_) * H_ + h];

    float vv = 0.f, vtr = 0.f;

    for (int t0 = 0; t0 < T_; t0 += K4_BLK) {
        // ---- cross phase: acc[j] = sum_{s < t0} A[t0+j][s] * vtr_s[s] ----
        float acc[K4_BLK];
#pragma unroll
        for (int j = 0; j < K4_BLK; j++) acc[j] = 0.f;

        for (int s4 = 0; s4 < t0; s4 += 4) {
            float v0 = vtr_s[(s4 + 0) * K4_THREADS + tid];
            float v1 = vtr_s[(s4 + 1) * K4_THREADS + tid];
            float v2 = vtr_s[(s4 + 2) * K4_THREADS + tid];
            float v3 = vtr_s[(s4 + 3) * K4_THREADS + tid];
#pragma unroll
            for (int j = 0; j < K4_BLK; j++) {
                float4 a = *(const float4*)&A_s[(t0 + j) * T_ + s4];  // broadcast
                acc[j] = fmaf(a.x, v0, acc[j]);
                acc[j] = fmaf(a.y, v1, acc[j]);
                acc[j] = fmaf(a.z, v2, acc[j]);
                acc[j] = fmaf(a.w, v3, acc[j]);
            }
        }

        // ---- intra phase: sequential over the 16 t's of this block ----
#pragma unroll
        for (int j = 0; j < K4_BLK; j++) {
            const int t = t0 + j;
            float a = acc[j];
            const float* Arow = &A_s[t * T_];
            for (int s = t0; s < t; s++)
                a = fmaf(Arow[s], vtr_s[s * K4_THREADS + tid], a);
            float ikv = CIKV_ * a;

            vv = ALPHA_ * vv + OMA_ * (ivp[t * H2_] + ikv);
            float val = tanh_fast(vv);
            valso[t * H_] = val;
            vtr = DTR_ * vtr + OMD_ * val;
            vtr_s[t * K4_THREADS + tid] = vtr;  // read only by this thread
            vtrg[t * H_] = vtr;
        }
    }
}

// ---------------------------------------------------------------------------
// K5: final memory GEMM.  mem[b][i][j] = eta * sum_s vtr[b,s,i]*ktr[b,s,j]
// ---------------------------------------------------------------------------
__global__ __launch_bounds__(256) void k5_gemm_mem(float* __restrict__ out)
{
    __shared__ float As[32][128];  // [s][i]
    __shared__ float Bs[32][128];  // [s][j]

    const int b  = blockIdx.z;
    const int i0 = blockIdx.y * 128;
    const int j0 = blockIdx.x * 128;
    const int tid = threadIdx.x;
    const int tr = tid >> 4;
    const int tc = tid & 15;

    const float* vtrb = &g_vtr[b * T_ * H_];
    const float* ktrb = &g_ktr[b * T_ * H_];

    float acc[8][8];
#pragma unroll
    for (int i = 0; i < 8; i++)
#pragma unroll
        for (int j = 0; j < 8; j++) acc[i][j] = 0.f;

    for (int s0 = 0; s0 < T_; s0 += 32) {
#pragma unroll
        for (int l = 0; l < 4; l++) {
            int idx = tid + l * 256;
            int s  = idx >> 5;
            int c4 = idx & 31;
            *(float4*)&As[s][c4 * 4] =
                *(const float4*)&vtrb[(s0 + s) * H_ + i0 + c4 * 4];
        }
#pragma unroll
        for (int l = 0; l < 4; l++) {
            int idx = tid + l * 256;
            int s  = idx >> 5;
            int c4 = idx & 31;
            *(float4*)&Bs[s][c4 * 4] =
                *(const float4*)&ktrb[(s0 + s) * H_ + j0 + c4 * 4];
        }
        __syncthreads();
#pragma unroll
        for (int k = 0; k < 32; k++) {
            float4 a0 = *(const float4*)&As[k][tr * 8];
            float4 a1 = *(const float4*)&As[k][tr * 8 + 4];
            float4 b0 = *(const float4*)&Bs[k][tc * 8];
            float4 b1 = *(const float4*)&Bs[k][tc * 8 + 4];
            float a[8] = {a0.x, a0.y, a0.z, a0.w, a1.x, a1.y, a1.z, a1.w};
            float bb[8] = {b0.x, b0.y, b0.z, b0.w, b1.x, b1.y, b1.z, b1.w};
#pragma unroll
            for (int i = 0; i < 8; i++)
#pragma unroll
                for (int j = 0; j < 8; j++) acc[i][j] = fmaf(a[i], bb[j], acc[i][j]);
        }
        __syncthreads();
    }

#pragma unroll
    for (int i = 0; i < 8; i++) {
        float* dst = &out[(size_t)b * (H_ * H_) + (i0 + tr * 8 + i) * H_ + j0 + tc * 8];
        *(float4*)&dst[0] = make_float4(ETA_ * acc[i][0], ETA_ * acc[i][1],
                                        ETA_ * acc[i][2], ETA_ * acc[i][3]);
        *(float4*)&dst[4] = make_float4(ETA_ * acc[i][4], ETA_ * acc[i][5],
                                        ETA_ * acc[i][6], ETA_ * acc[i][7]);
    }
}

// ---------------------------------------------------------------------------
extern "C" void kernel_launch(void* const* d_in, const int* in_sizes, int n_in,
                              void* d_out, int out_size)
{
    const float* x = (const float*)d_in[0];   // (32,128,256)
    const float* W = (const float*)d_in[1];   // (1536,256)
    float* out = (float*)d_out;               // mem | keys | vals

    // K4 needs 192KB dynamic smem (A 64KB + vtr history 128KB).
    (void)cudaFuncSetAttribute(k4_scan_val,
                               cudaFuncAttributeMaxDynamicSharedMemorySize,
                               196608);

    k1_gemm_in<<<dim3(12, 32), 256>>>(x, W);
    k2_scan_key<<<96, 256>>>(out);
    k3_gemm_A<<<dim3(6, 32), 256>>>();
    k4_scan_val<<<96, K4_THREADS, 196608>>>(out);
    k5_gemm_mem<<<dim3(6, 6, 32), 256>>>(out);
}

// round 4
// speedup vs baseline: 2.3209x; 1.5125x over previous
#include <cuda_runtime.h>
#include <cuda_bf16.h>
#include <math.h>

// Problem constants
#define B_   32
#define T_   128
#define H_   768
#define IN_  256
#define H2_  1536

// exp(-1/20)
#define ALPHA_   0.951229424500714f
#define OMA_     0.048770575499286f
#define DTR_     0.951229424500714f
#define OMD_     0.048770575499286f
#define ETA_     0.1f
#define CIKV_    0.02f

// Output offsets (floats): mem | keys | vals
#define OUT_MEM_   0
#define OUT_KEYS_  18874368
#define OUT_VALS_  22020096

// Scratch
__device__ float g_i[B_ * T_ * H2_];
__device__ float g_key[B_ * T_ * H_];
__device__ float g_ktr[B_ * T_ * H_];
__device__ float g_vtr[B_ * T_ * H_];
__device__ float g_Apart[6 * B_ * T_ * T_];

__device__ __forceinline__ float tanh_fast(float x) {
    float y;
    asm("tanh.approx.f32 %0, %1;" : "=f"(y) : "f"(x));
    return y;
}

// ---------------------------------------------------------------------------
// mma.sync helpers (bf16 hi/lo split GEMM)
// ---------------------------------------------------------------------------
__device__ __forceinline__ void ldsm_x4(unsigned addr, unsigned& r0, unsigned& r1,
                                        unsigned& r2, unsigned& r3) {
    asm volatile("ldmatrix.sync.aligned.m8n8.x4.shared.b16 {%0,%1,%2,%3}, [%4];"
                 : "=r"(r0), "=r"(r1), "=r"(r2), "=r"(r3) : "r"(addr));
}
__device__ __forceinline__ void ldsm_x4t(unsigned addr, unsigned& r0, unsigned& r1,
                                         unsigned& r2, unsigned& r3) {
    asm volatile("ldmatrix.sync.aligned.m8n8.x4.trans.shared.b16 {%0,%1,%2,%3}, [%4];"
                 : "=r"(r0), "=r"(r1), "=r"(r2), "=r"(r3) : "r"(addr));
}
__device__ __forceinline__ void mma16816(float* c, unsigned a0, unsigned a1,
                                         unsigned a2, unsigned a3,
                                         unsigned b0, unsigned b1) {
    asm volatile(
        "mma.sync.aligned.m16n8k16.row.col.f32.bf16.bf16.f32 "
        "{%0,%1,%2,%3}, {%4,%5,%6,%7}, {%8,%9}, {%0,%1,%2,%3};"
        : "+f"(c[0]), "+f"(c[1]), "+f"(c[2]), "+f"(c[3])
        : "r"(a0), "r"(a1), "r"(a2), "r"(a3), "r"(b0), "r"(b1));
}
__device__ __forceinline__ void split_bf16(float v, __nv_bfloat16& hi, __nv_bfloat16& lo) {
    hi = __float2bfloat16(v);
    lo = __float2bfloat16(v - __bfloat162float(hi));
}

#define SRM 40    // smem stride (halves) for row-major [m][k] tiles (128x32)
#define SKM 136   // smem stride (halves) for k-major [k][m] tiles (32x128)

// One BK=32 compute step: row-major smem tiles [128][SRM], no-trans ldmatrix.
__device__ __forceinline__ void mma_step_rm(
    unsigned bAh, unsigned bAl, unsigned bBh, unsigned bBl,
    int wm, int wn, int lane, float acc[4][4][4])
{
    const int lr = lane & 15;
    const int kh = (lane >> 4) * 8;
#pragma unroll
    for (int ks = 0; ks < 32; ks += 16) {
        unsigned ah[4][4], al[4][4], bh[4][2], bl[4][2];
#pragma unroll
        for (int i = 0; i < 4; i++) {
            unsigned off = 2u * ((wm * 64 + i * 16 + lr) * SRM + ks + kh);
            ldsm_x4(bAh + off, ah[i][0], ah[i][1], ah[i][2], ah[i][3]);
            ldsm_x4(bAl + off, al[i][0], al[i][1], al[i][2], al[i][3]);
        }
#pragma unroll
        for (int p = 0; p < 2; p++) {
            unsigned off = 2u * ((wn * 32 + p * 16 + lr) * SRM + ks + kh);
            unsigned r0, r1, r2, r3;
            ldsm_x4(bBh + off, r0, r1, r2, r3);
            bh[p * 2 + 0][0] = r0; bh[p * 2 + 0][1] = r2;
            bh[p * 2 + 1][0] = r1; bh[p * 2 + 1][1] = r3;
            ldsm_x4(bBl + off, r0, r1, r2, r3);
            bl[p * 2 + 0][0] = r0; bl[p * 2 + 0][1] = r2;
            bl[p * 2 + 1][0] = r1; bl[p * 2 + 1][1] = r3;
        }
#pragma unroll
        for (int i = 0; i < 4; i++)
#pragma unroll
            for (int j = 0; j < 4; j++) {
                mma16816(acc[i][j], ah[i][0], ah[i][1], ah[i][2], ah[i][3],
                         bh[j][0], bh[j][1]);
                mma16816(acc[i][j], ah[i][0], ah[i][1], ah[i][2], ah[i][3],
                         bl[j][0], bl[j][1]);
                mma16816(acc[i][j], al[i][0], al[i][1], al[i][2], al[i][3],
                         bh[j][0], bh[j][1]);
            }
    }
}

// One BK=32 compute step: k-major smem tiles [32][SKM], trans ldmatrix.
__device__ __forceinline__ void mma_step_km(
    unsigned bAh, unsigned bAl, unsigned bBh, unsigned bBl,
    int wm, int wn, int lane, float acc[4][4][4])
{
    const int krow = (lane & 7) + ((lane >> 4) << 3);
    const int mcol = ((lane >> 3) & 1) * 8;
#pragma unroll
    for (int ks = 0; ks < 32; ks += 16) {
        unsigned ah[4][4], al[4][4], bh[4][2], bl[4][2];
#pragma unroll
        for (int i = 0; i < 4; i++) {
            unsigned off = 2u * ((ks + krow) * SKM + wm * 64 + i * 16 + mcol);
            ldsm_x4t(bAh + off, ah[i][0], ah[i][1], ah[i][2], ah[i][3]);
            ldsm_x4t(bAl + off, al[i][0], al[i][1], al[i][2], al[i][3]);
        }
#pragma unroll
        for (int p = 0; p < 2; p++) {
            unsigned off = 2u * ((ks + krow) * SKM + wn * 32 + p * 16 + mcol);
            unsigned r0, r1, r2, r3;
            ldsm_x4t(bBh + off, r0, r1, r2, r3);
            bh[p * 2 + 0][0] = r0; bh[p * 2 + 0][1] = r2;
            bh[p * 2 + 1][0] = r1; bh[p * 2 + 1][1] = r3;
            ldsm_x4t(bBl + off, r0, r1, r2, r3);
            bl[p * 2 + 0][0] = r0; bl[p * 2 + 0][1] = r2;
            bl[p * 2 + 1][0] = r1; bl[p * 2 + 1][1] = r3;
        }
#pragma unroll
        for (int i = 0; i < 4; i++)
#pragma unroll
            for (int j = 0; j < 4; j++) {
                mma16816(acc[i][j], ah[i][0], ah[i][1], ah[i][2], ah[i][3],
                         bh[j][0], bh[j][1]);
                mma16816(acc[i][j], ah[i][0], ah[i][1], ah[i][2], ah[i][3],
                         bl[j][0], bl[j][1]);
                mma16816(acc[i][j], al[i][0], al[i][1], al[i][2], al[i][3],
                         bh[j][0], bh[j][1]);
            }
    }
}

// Row-major loader: 128 rows x 32 k from gmem (ld = row stride in f32).
__device__ __forceinline__ void load_rm(const float* __restrict__ src, int ld,
                                        __nv_bfloat16* sh, __nv_bfloat16* sl,
                                        int tid)
{
#pragma unroll
    for (int l = 0; l < 4; l++) {
        int idx = tid + l * 256;
        int row = idx >> 3;
        int c4  = idx & 7;
        float4 v = *(const float4*)&src[row * ld + c4 * 4];
        __nv_bfloat16 h0, l0, h1, l1, h2, l2, h3, l3;
        split_bf16(v.x, h0, l0); split_bf16(v.y, h1, l1);
        split_bf16(v.z, h2, l2); split_bf16(v.w, h3, l3);
        int o = row * SRM + c4 * 4;
        sh[o + 0] = h0; sh[o + 1] = h1; sh[o + 2] = h2; sh[o + 3] = h3;
        sl[o + 0] = l0; sl[o + 1] = l1; sl[o + 2] = l2; sl[o + 3] = l3;
    }
}

// K-major loader: 32 k-rows x 128 m from gmem [k][m] (ld = k-row stride in f32).
__device__ __forceinline__ void load_km(const float* __restrict__ src, int ld,
                                        __nv_bfloat16* sh, __nv_bfloat16* sl,
                                        int tid)
{
#pragma unroll
    for (int l = 0; l < 4; l++) {
        int idx = tid + l * 256;
        int s = idx >> 5;
        int q = idx & 31;
        float4 v = *(const float4*)&src[s * ld + q * 4];
        __nv_bfloat16 h0, l0, h1, l1, h2, l2, h3, l3;
        split_bf16(v.x, h0, l0); split_bf16(v.y, h1, l1);
        split_bf16(v.z, h2, l2); split_bf16(v.w, h3, l3);
        int o = s * SKM + q * 4;
        sh[o + 0] = h0; sh[o + 1] = h1; sh[o + 2] = h2; sh[o + 3] = h3;
        sl[o + 0] = l0; sl[o + 1] = l1; sl[o + 2] = l2; sl[o + 3] = l3;
    }
}

// Epilogue: write 4x4 m16n8 tiles to gmem (ldc f32 row stride), scaled.
__device__ __forceinline__ void epilogue(float* dst, int ldc, float scale,
                                         int wm, int wn, int lane,
                                         float acc[4][4][4])
{
    const int r0 = lane >> 2;
    const int c0 = (lane & 3) * 2;
#pragma unroll
    for (int i = 0; i < 4; i++)
#pragma unroll
        for (int j = 0; j < 4; j++) {
            int row = wm * 64 + i * 16 + r0;
            int col = wn * 32 + j * 8 + c0;
            float2 v0 = make_float2(scale * acc[i][j][0], scale * acc[i][j][1]);
            float2 v1 = make_float2(scale * acc[i][j][2], scale * acc[i][j][3]);
            *(float2*)&dst[row * ldc + col] = v0;
            *(float2*)&dst[(row + 8) * ldc + col] = v1;
        }
}

// ---------------------------------------------------------------------------
// K1: g_i[m][n] = sum_k x[m][k] * W[n][k]   M=4096 N=1536 K=256
// ---------------------------------------------------------------------------
__global__ __launch_bounds__(256) void k1_gemm_in(
    const float* __restrict__ x, const float* __restrict__ W)
{
    __shared__ __nv_bfloat16 sAh[128 * SRM], sAl[128 * SRM];
    __shared__ __nv_bfloat16 sBh[128 * SRM], sBl[128 * SRM];

    const int m0 = blockIdx.y * 128;
    const int n0 = blockIdx.x * 128;
    const int tid = threadIdx.x;
    const int warp = tid >> 5, lane = tid & 31;
    const int wm = warp >> 2, wn = warp & 3;

    unsigned bAh = (unsigned)__cvta_generic_to_shared(sAh);
    unsigned bAl = (unsigned)__cvta_generic_to_shared(sAl);
    unsigned bBh = (unsigned)__cvta_generic_to_shared(sBh);
    unsigned bBl = (unsigned)__cvta_generic_to_shared(sBl);

    float acc[4][4][4];
#pragma unroll
    for (int i = 0; i < 4; i++)
#pragma unroll
        for (int j = 0; j < 4; j++)
#pragma unroll
            for (int r = 0; r < 4; r++) acc[i][j][r] = 0.f;

    for (int k0 = 0; k0 < IN_; k0 += 32) {
        load_rm(&x[(size_t)m0 * IN_ + k0], IN_, sAh, sAl, tid);
        load_rm(&W[(size_t)n0 * IN_ + k0], IN_, sBh, sBl, tid);
        __syncthreads();
        mma_step_rm(bAh, bAl, bBh, bBl, wm, wn, lane, acc);
        __syncthreads();
    }
    epilogue(&g_i[(size_t)m0 * H2_ + n0], H2_, 1.f, wm, wn, lane, acc);
}

// ---------------------------------------------------------------------------
// K2: key-side elementwise scan (unchanged)
// ---------------------------------------------------------------------------
__global__ __launch_bounds__(256) void k2_scan_key(float* __restrict__ out)
{
    const int b  = blockIdx.x / 3;
    const int h  = (blockIdx.x % 3) * 256 + threadIdx.x;

    const float* ik = &g_i[(b * T_) * H2_ + h];
    float* keyp  = &g_key[(b * T_) * H_ + h];
    float* ktrp  = &g_ktr[(b * T_) * H_ + h];
    float* keyso = &out[OUT_KEYS_ + (b * T_) * H_ + h];

    float kv = 0.f, ktr = 0.f;
#pragma unroll 4
    for (int t = 0; t < T_; t++) {
        kv = ALPHA_ * kv + OMA_ * ik[t * H2_];
        float key = tanh_fast(kv);
        ktr = DTR_ * ktr + OMD_ * key;
        keyp[t * H_]  = key;
        ktrp[t * H_]  = ktr;
        keyso[t * H_] = key;
    }
}

// ---------------------------------------------------------------------------
// K3: Apart[p][b][t][s] = sum_{k in chunk p} key[b,t,k]*ktr[b,s,k]
//     grid (6,32). M=N=128, K=128.
// ---------------------------------------------------------------------------
__global__ __launch_bounds__(256) void k3_gemm_A()
{
    __shared__ __nv_bfloat16 sAh[128 * SRM], sAl[128 * SRM];
    __shared__ __nv_bfloat16 sBh[128 * SRM], sBl[128 * SRM];

    const int p = blockIdx.x;
    const int b = blockIdx.y;
    const int tid = threadIdx.x;
    const int warp = tid >> 5, lane = tid & 31;
    const int wm = warp >> 2, wn = warp & 3;

    unsigned bAh = (unsigned)__cvta_generic_to_shared(sAh);
    unsigned bAl = (unsigned)__cvta_generic_to_shared(sAl);
    unsigned bBh = (unsigned)__cvta_generic_to_shared(sBh);
    unsigned bBl = (unsigned)__cvta_generic_to_shared(sBl);

    const float* keyb = &g_key[(size_t)b * T_ * H_ + p * 128];
    const float* ktrb = &g_ktr[(size_t)b * T_ * H_ + p * 128];

    float acc[4][4][4];
#pragma unroll
    for (int i = 0; i < 4; i++)
#pragma unroll
        for (int j = 0; j < 4; j++)
#pragma unroll
            for (int r = 0; r < 4; r++) acc[i][j][r] = 0.f;

    for (int k0 = 0; k0 < 128; k0 += 32) {
        load_rm(&keyb[k0], H_, sAh, sAl, tid);
        load_rm(&ktrb[k0], H_, sBh, sBl, tid);
        __syncthreads();
        mma_step_rm(bAh, bAl, bBh, bBl, wm, wn, lane, acc);
        __syncthreads();
    }
    epilogue(&g_Apart[(size_t)(p * B_ + b) * (T_ * T_)], T_, 1.f, wm, wn, lane, acc);
}

// ---------------------------------------------------------------------------
// K4: value-side blocked sequential scan (unchanged from R2)
// ---------------------------------------------------------------------------
#define K4_THREADS 256
#define K4_BLK 16

__global__ __launch_bounds__(K4_THREADS) void k4_scan_val(float* __restrict__ out)
{
    extern __shared__ float sm[];
    float* A_s   = sm;
    float* vtr_s = sm + T_ * T_;

    const int b   = blockIdx.x / 3;
    const int hb  = blockIdx.x % 3;
    const int tid = threadIdx.x;
    const int h   = hb * K4_THREADS + tid;

    {
        const float* ap = &g_Apart[(size_t)b * (T_ * T_)];
        for (int e = tid * 4; e < T_ * T_; e += K4_THREADS * 4) {
            float4 s = *(const float4*)&ap[e];
#pragma unroll
            for (int p = 1; p < 6; p++) {
                float4 v = *(const float4*)&ap[(size_t)p * B_ * T_ * T_ + e];
                s.x += v.x; s.y += v.y; s.z += v.z; s.w += v.w;
            }
            *(float4*)&A_s[e] = s;
        }
    }
    __syncthreads();

    const float* ivp = &g_i[b * T_ * H2_ + H_ + h];
    float* valso = &out[OUT_VALS_ + (b * T_) * H_ + h];
    float* vtrg  = &g_vtr[(b * T_) * H_ + h];

    float vv = 0.f, vtr = 0.f;

    for (int t0 = 0; t0 < T_; t0 += K4_BLK) {
        float acc[K4_BLK];
#pragma unroll
        for (int j = 0; j < K4_BLK; j++) acc[j] = 0.f;

        for (int s4 = 0; s4 < t0; s4 += 4) {
            float v0 = vtr_s[(s4 + 0) * K4_THREADS + tid];
            float v1 = vtr_s[(s4 + 1) * K4_THREADS + tid];
            float v2 = vtr_s[(s4 + 2) * K4_THREADS + tid];
            float v3 = vtr_s[(s4 + 3) * K4_THREADS + tid];
#pragma unroll
            for (int j = 0; j < K4_BLK; j++) {
                float4 a = *(const float4*)&A_s[(t0 + j) * T_ + s4];
                acc[j] = fmaf(a.x, v0, acc[j]);
                acc[j] = fmaf(a.y, v1, acc[j]);
                acc[j] = fmaf(a.z, v2, acc[j]);
                acc[j] = fmaf(a.w, v3, acc[j]);
            }
        }

#pragma unroll
        for (int j = 0; j < K4_BLK; j++) {
            const int t = t0 + j;
            float a = acc[j];
            const float* Arow = &A_s[t * T_];
            for (int s = t0; s < t; s++)
                a = fmaf(Arow[s], vtr_s[s * K4_THREADS + tid], a);
            float ikv = CIKV_ * a;

            vv = ALPHA_ * vv + OMA_ * (ivp[t * H2_] + ikv);
            float val = tanh_fast(vv);
            valso[t * H_] = val;
            vtr = DTR_ * vtr + OMD_ * val;
            vtr_s[t * K4_THREADS + tid] = vtr;
            vtrg[t * H_] = vtr;
        }
    }
}

// ---------------------------------------------------------------------------
// K5: mem[b][i][j] = eta * sum_s vtr[b,s,i]*ktr[b,s,j]
//     Operands are [s][h] (k-major) -> trans-ldmatrix path. grid (6,6,32).
// ---------------------------------------------------------------------------
__global__ __launch_bounds__(256) void k5_gemm_mem(float* __restrict__ out)
{
    __shared__ __nv_bfloat16 sAh[32 * SKM], sAl[32 * SKM];
    __shared__ __nv_bfloat16 sBh[32 * SKM], sBl[32 * SKM];

    const int b  = blockIdx.z;
    const int i0 = blockIdx.y * 128;
    const int j0 = blockIdx.x * 128;
    const int tid = threadIdx.x;
    const int warp = tid >> 5, lane = tid & 31;
    const int wm = warp >> 2, wn = warp & 3;

    unsigned bAh = (unsigned)__cvta_generic_to_shared(sAh);
    unsigned bAl = (unsigned)__cvta_generic_to_shared(sAl);
    unsigned bBh = (unsigned)__cvta_generic_to_shared(sBh);
    unsigned bBl = (unsigned)__cvta_generic_to_shared(sBl);

    const float* vtrb = &g_vtr[(size_t)b * T_ * H_];
    const float* ktrb = &g_ktr[(size_t)b * T_ * H_];

    float acc[4][4][4];
#pragma unroll
    for (int i = 0; i < 4; i++)
#pragma unroll
        for (int j = 0; j < 4; j++)
#pragma unroll
            for (int r = 0; r < 4; r++) acc[i][j][r] = 0.f;

    for (int s0 = 0; s0 < T_; s0 += 32) {
        load_km(&vtrb[(size_t)s0 * H_ + i0], H_, sAh, sAl, tid);
        load_km(&ktrb[(size_t)s0 * H_ + j0], H_, sBh, sBl, tid);
        __syncthreads();
        mma_step_km(bAh, bAl, bBh, bBl, wm, wn, lane, acc);
        __syncthreads();
    }
    epilogue(&out[(size_t)b * (H_ * H_) + (size_t)i0 * H_ + j0], H_, ETA_,
             wm, wn, lane, acc);
}

// ---------------------------------------------------------------------------
extern "C" void kernel_launch(void* const* d_in, const int* in_sizes, int n_in,
                              void* d_out, int out_size)
{
    const float* x = (const float*)d_in[0];   // (32,128,256)
    const float* W = (const float*)d_in[1];   // (1536,256)
    float* out = (float*)d_out;               // mem | keys | vals

    (void)cudaFuncSetAttribute(k4_scan_val,
                               cudaFuncAttributeMaxDynamicSharedMemorySize,
                               196608);

    k1_gemm_in<<<dim3(12, 32), 256>>>(x, W);
    k2_scan_key<<<96, 256>>>(out);
    k3_gemm_A<<<dim3(6, 32), 256>>>();
    k4_scan_val<<<96, K4_THREADS, 196608>>>(out);
    k5_gemm_mem<<<dim3(6, 6, 32), 256>>>(out);
}